// round 8
// baseline (speedup 1.0000x reference)
#include <cuda_runtime.h>

#define NB   16
#define WIN  128
#define KF   256
#define EMB  256

typedef unsigned long long u64;

#define ADD2(d, a, b) asm("add.rn.f32x2 %0, %1, %2;" : "=l"(d) : "l"(a), "l"(b))
#define FMA2(d, a, b, c) asm("fma.rn.f32x2 %0, %1, %2, %3;" : "=l"(d) : "l"(a), "l"(b), "l"(c))
#define UNPK(lo, hi, v) asm("mov.b64 {%0, %1}, %2;" : "=f"(lo), "=f"(hi) : "l"(v))
#define PK(d, lo, hi) asm("mov.b64 %0, {%1, %2};" : "=l"(d) : "f"(lo), "f"(hi))

#define ABSMASK 0x7FFFFFFF7FFFFFFFull

// ---------------- device scratch --------------------------------------------
__device__ float g_UI[NB * KF * EMB];        // hi + lin_b
__device__ float g_HJ[NB * KF * EMB];        // hj
__device__ float g_ATT[NB * KF * KF];        // exp(e - m_tile), per 64-j tile
__device__ float g_MS[NB * KF * 4 * 2];      // per (row, j-tile): max, sumexp

// ============================================================================
// gemmA: fused N=512 GEMM; e'<256 -> UI (+lb), e'>=256 -> HJ.
// Tile 64 rows x 64 e', 256 threads, micro 4x4, K=128 (LDS.128 steps of 4).
// smem 67.6KB -> 3 CTAs/SM (24 warps). Grid 512.
// ============================================================================
#define XP 132   // pitch: mult of 4 (16B rows); 132%32=4
__global__ __launch_bounds__(256, 3)
void gemmA(const float* __restrict__ x, const float* __restrict__ lw,
           const float* __restrict__ lb)
{
    extern __shared__ float sm[];
    float* sXT = sm;                  // [64 k][132]  (w along row)
    float* sW  = sXT + 64 * XP;       // [64 e'][132]

    const int ktile = blockIdx.y;             // 0..63
    const int b  = ktile >> 2;
    const int k0 = (ktile & 3) * 64;
    const int ep = blockIdx.x * 64;           // 0..448
    const int side = (ep >= 256);
    const int eb   = ep & 255;
    const int woff = side ? WIN : 0;
    const int t  = threadIdx.x;

    const float* xb = x + (size_t)b * WIN * KF + k0;
    for (int idx = t; idx < 128 * 64; idx += 256) {
        int w = idx >> 6, kk = idx & 63;
        sXT[kk * XP + w] = xb[w * KF + kk];
    }
    for (int idx = t; idx < 64 * 128; idx += 256) {
        int ee = idx >> 7, w = idx & 127;
        sW[ee * XP + w] = lw[(eb + ee) * (2 * WIN) + woff + w];
    }
    __syncthreads();

    const int tk = t & 15;   // k rows: tk + ii*16  (ii<4)
    const int te = t >> 4;   // e' cols: te + jj*16 (jj<4)
    const ulonglong2* xq[4];  const ulonglong2* wq[4];
    #pragma unroll
    for (int ii = 0; ii < 4; ++ii) xq[ii] = (const ulonglong2*)(sXT + (tk + ii * 16) * XP);
    #pragma unroll
    for (int jj = 0; jj < 4; ++jj) wq[jj] = (const ulonglong2*)(sW + (te + jj * 16) * XP);

    u64 acc[4][4];
    #pragma unroll
    for (int ii = 0; ii < 4; ++ii)
        #pragma unroll
        for (int jj = 0; jj < 4; ++jj) acc[ii][jj] = 0ull;

    #pragma unroll 4
    for (int s = 0; s < 32; ++s) {           // 4 w per step
        ulonglong2 xv[4], wv[4];
        #pragma unroll
        for (int ii = 0; ii < 4; ++ii) xv[ii] = xq[ii][s];
        #pragma unroll
        for (int jj = 0; jj < 4; ++jj) wv[jj] = wq[jj][s];
        #pragma unroll
        for (int ii = 0; ii < 4; ++ii)
            #pragma unroll
            for (int jj = 0; jj < 4; ++jj) {
                FMA2(acc[ii][jj], xv[ii].x, wv[jj].x, acc[ii][jj]);
                FMA2(acc[ii][jj], xv[ii].y, wv[jj].y, acc[ii][jj]);
            }
    }

    float lbv[4];
    #pragma unroll
    for (int jj = 0; jj < 4; ++jj)
        lbv[jj] = side ? 0.f : __ldg(lb + eb + te + jj * 16);

    float* sO = sm;                  // reuse: [64][132]
    __syncthreads();
    #pragma unroll
    for (int ii = 0; ii < 4; ++ii)
        #pragma unroll
        for (int jj = 0; jj < 4; ++jj) {
            float lo, hi; UNPK(lo, hi, acc[ii][jj]);
            sO[(tk + ii * 16) * XP + te + jj * 16] = lo + hi + lbv[jj];
        }
    __syncthreads();
    float* dst = (side ? g_HJ : g_UI) + ((size_t)b * KF + k0) * EMB + eb;
    for (int idx = t; idx < 64 * 32; idx += 256) {
        int r = idx >> 5, c = idx & 31;
        *(float2*)(dst + (size_t)r * EMB + c * 2) = *(float2*)(sO + r * XP + c * 2);
    }
}

// ============================================================================
// kernB: e = 0.6(dot_i+dot_j) + sum 0.4a|u+v| + bias; store exp(e - m_tile);
// partials -> g_MS. Double-buffered hot loop (prefetch s+1 before math of s).
// ============================================================================
#define BP 260   // mult of 4; 260%32=4
__global__ __launch_bounds__(256, 2)
void kernB(const float* __restrict__ a, const float* __restrict__ ab)
{
    extern __shared__ float sm[];
    float* sUI = sm;                   // [32][260]
    float* sHJ = sUI + 32 * BP;        // [64][260]
    float* sA4 = sHJ + 64 * BP;        // [256]  0.4*a
    float* sAI = sA4 + 256;            // [32]
    float* sAJ = sAI + 32;             // [64]

    const int b  = blockIdx.z;
    const int i0 = blockIdx.y * 32;
    const int jt = blockIdx.x;
    const int j0 = jt * 64;
    const int t  = threadIdx.x;

    const float4* gu = (const float4*)(g_UI + ((size_t)b * KF + i0) * EMB);
    for (int idx = t; idx < 32 * 64; idx += 256) {
        int r = idx >> 6, c = idx & 63;
        *(float4*)(sUI + r * BP + c * 4) = gu[r * 64 + c];
    }
    const float4* gh = (const float4*)(g_HJ + ((size_t)b * KF + j0) * EMB);
    for (int idx = t; idx < 64 * 64; idx += 256) {
        int r = idx >> 6, c = idx & 63;
        *(float4*)(sHJ + r * BP + c * 4) = gh[r * 64 + c];
    }
    sA4[t] = 0.4f * a[t];
    __syncthreads();

    // row dots: 0.6*dot(row, a) = 1.5*dot(row, 0.4a)
    {
        const int warp = t >> 5, lane = t & 31;
        #pragma unroll
        for (int rr = 0; rr < 4; ++rr) {
            int r = warp * 4 + rr;
            float s = 0.f;
            #pragma unroll
            for (int q = 0; q < 8; ++q) s += sUI[r * BP + lane + q * 32] * sA4[lane + q * 32];
            #pragma unroll
            for (int off = 16; off; off >>= 1) s += __shfl_xor_sync(0xffffffffu, s, off);
            if (lane == 0) sAI[r] = 1.5f * s;
        }
        #pragma unroll
        for (int rr = 0; rr < 8; ++rr) {
            int r = warp * 8 + rr;
            float s = 0.f;
            #pragma unroll
            for (int q = 0; q < 8; ++q) s += sHJ[r * BP + lane + q * 32] * sA4[lane + q * 32];
            #pragma unroll
            for (int off = 16; off; off >>= 1) s += __shfl_xor_sync(0xffffffffu, s, off);
            if (lane == 0) sAJ[r] = 1.5f * s;
        }
    }
    __syncthreads();

    const int ti = t >> 4;
    const int jl = t & 15;
    const ulonglong2* uq0 = (const ulonglong2*)(sUI + ti * BP);
    const ulonglong2* uq1 = (const ulonglong2*)(sUI + (ti + 16) * BP);
    const ulonglong2* vq[4];
    #pragma unroll
    for (int q = 0; q < 4; ++q) vq[q] = (const ulonglong2*)(sHJ + (jl + q * 16) * BP);
    const ulonglong2* aq = (const ulonglong2*)sA4;

    u64 acc0[4], acc1[4];
    #pragma unroll
    for (int q = 0; q < 4; ++q) { acc0[q] = 0ull; acc1[q] = 0ull; }

    // double-buffered: prefetch step s+1 while computing step s
    ulonglong2 aeB[2], u0B[2], u1B[2], vB[2][4];
    aeB[0] = aq[0]; u0B[0] = uq0[0]; u1B[0] = uq1[0];
    #pragma unroll
    for (int q = 0; q < 4; ++q) vB[0][q] = vq[q][0];

    #pragma unroll 2
    for (int s = 0; s < 64; ++s) {
        const int cur = s & 1, nxt = cur ^ 1;
        if (s < 63) {
            aeB[nxt] = aq[s + 1]; u0B[nxt] = uq0[s + 1]; u1B[nxt] = uq1[s + 1];
            #pragma unroll
            for (int q = 0; q < 4; ++q) vB[nxt][q] = vq[q][s + 1];
        }
        ulonglong2 ae = aeB[cur], u0 = u0B[cur], u1 = u1B[cur];
        #pragma unroll
        for (int q = 0; q < 4; ++q) {
            ulonglong2 v = vB[cur][q];
            u64 s0x, s0y, s1x, s1y;
            ADD2(s0x, u0.x, v.x); ADD2(s0y, u0.y, v.y);
            ADD2(s1x, u1.x, v.x); ADD2(s1y, u1.y, v.y);
            s0x &= ABSMASK; s0y &= ABSMASK;
            s1x &= ABSMASK; s1y &= ABSMASK;
            FMA2(acc0[q], s0x, ae.x, acc0[q]);
            FMA2(acc0[q], s0y, ae.y, acc0[q]);
            FMA2(acc1[q], s1x, ae.x, acc1[q]);
            FMA2(acc1[q], s1y, ae.y, acc1[q]);
        }
    }

    // epilogue: final e, tile softmax partials, exp, staged store
    const float ai0 = sAI[ti], ai1 = sAI[ti + 16];
    float v0[4], v1[4];
    #pragma unroll
    for (int q = 0; q < 4; ++q) {
        int jc = jl + q * 16;
        int j  = j0 + jc;
        float lo, hi;
        UNPK(lo, hi, acc0[q]);
        v0[q] = lo + hi + ai0 + sAJ[jc] + ab[(size_t)(i0 + ti) * KF + j];
        UNPK(lo, hi, acc1[q]);
        v1[q] = lo + hi + ai1 + sAJ[jc] + ab[(size_t)(i0 + ti + 16) * KF + j];
    }
    float m0 = fmaxf(fmaxf(v0[0], v0[1]), fmaxf(v0[2], v0[3]));
    float m1 = fmaxf(fmaxf(v1[0], v1[1]), fmaxf(v1[2], v1[3]));
    #pragma unroll
    for (int off = 8; off; off >>= 1) {
        m0 = fmaxf(m0, __shfl_xor_sync(0xffffffffu, m0, off));
        m1 = fmaxf(m1, __shfl_xor_sync(0xffffffffu, m1, off));
    }
    float e0[4], e1[4];
    float s0 = 0.f, s1 = 0.f;
    #pragma unroll
    for (int q = 0; q < 4; ++q) {
        e0[q] = __expf(v0[q] - m0); s0 += e0[q];
        e1[q] = __expf(v1[q] - m1); s1 += e1[q];
    }
    #pragma unroll
    for (int off = 8; off; off >>= 1) {
        s0 += __shfl_xor_sync(0xffffffffu, s0, off);
        s1 += __shfl_xor_sync(0xffffffffu, s1, off);
    }
    if (jl == 0) {
        size_t r0i = (size_t)(b * KF + i0 + ti) * 8 + jt * 2;
        size_t r1i = (size_t)(b * KF + i0 + ti + 16) * 8 + jt * 2;
        g_MS[r0i] = m0; g_MS[r0i + 1] = s0;
        g_MS[r1i] = m1; g_MS[r1i + 1] = s1;
    }

    float* sE = sm;                  // reuse sUI region
    __syncthreads();
    #pragma unroll
    for (int q = 0; q < 4; ++q) {
        int jc = jl + q * 16;
        sE[ti * 66 + jc]        = e0[q];
        sE[(ti + 16) * 66 + jc] = e1[q];
    }
    __syncthreads();
    for (int idx = t; idx < 32 * 64; idx += 256) {
        int r = idx >> 6, c = idx & 63;
        g_ATT[((size_t)b * KF + i0 + r) * KF + j0 + c] = sE[r * 66 + c];
    }
}

// ============================================================================
// kernC: out[b,w,i] = sigmoid( sum_jt corr[i,jt] * sum_j att'[i,j]*x[w,j] )
// Tile 32 i x 32 w, grid 512, ~27KB smem -> 4 CTAs/SM (32 warps).
// ============================================================================
#define CP 68    // mult of 4; 68%32=4
__global__ __launch_bounds__(256)
void kernC(const float* __restrict__ x, float* __restrict__ out)
{
    __shared__ float sAtt[32 * CP];
    __shared__ float sX[32 * CP];
    __shared__ float sOut[32 * CP];
    __shared__ float sCorr[32 * 4];

    const int b  = blockIdx.z;
    const int w0 = blockIdx.y * 32;
    const int i0 = blockIdx.x * 32;
    const int t  = threadIdx.x;
    const int il = t & 15;   // i: il, il+16
    const int tw = t >> 4;   // w: tw, tw+16

    if (t < 32) {
        const float* p = g_MS + (size_t)(b * KF + i0 + t) * 8;
        float m[4], s[4];
        #pragma unroll
        for (int q = 0; q < 4; ++q) { m[q] = p[q * 2]; s[q] = p[q * 2 + 1]; }
        float M = fmaxf(fmaxf(m[0], m[1]), fmaxf(m[2], m[3]));
        float ex[4];
        float S = 0.f;
        #pragma unroll
        for (int q = 0; q < 4; ++q) { ex[q] = __expf(m[q] - M); S += s[q] * ex[q]; }
        float inv = 1.0f / S;
        #pragma unroll
        for (int q = 0; q < 4; ++q) sCorr[t * 4 + q] = ex[q] * inv;
    }

    u64 acc[2][2];
    acc[0][0] = acc[0][1] = acc[1][0] = acc[1][1] = 0ull;

    for (int jt = 0; jt < 4; ++jt) {
        __syncthreads();
        const int j0 = jt * 64;
        for (int idx = t; idx < 32 * 16; idx += 256) {
            int r = idx >> 4, c = idx & 15;
            *(float4*)(sAtt + r * CP + c * 4) =
                *(const float4*)(g_ATT + ((size_t)b * KF + i0 + r) * KF + j0 + c * 4);
            *(float4*)(sX + r * CP + c * 4) =
                *(const float4*)(x + ((size_t)b * WIN + w0 + r) * KF + j0 + c * 4);
        }
        __syncthreads();

        const ulonglong2* xq0 = (const ulonglong2*)(sX + tw * CP);
        const ulonglong2* xq1 = (const ulonglong2*)(sX + (tw + 16) * CP);
        const ulonglong2* aq0 = (const ulonglong2*)(sAtt + il * CP);
        const ulonglong2* aq1 = (const ulonglong2*)(sAtt + (il + 16) * CP);

        u64 accP[2][2];
        accP[0][0] = accP[0][1] = accP[1][0] = accP[1][1] = 0ull;

        #pragma unroll 8
        for (int s = 0; s < 16; ++s) {       // 4 j per step
            ulonglong2 x0 = xq0[s], x1 = xq1[s];
            ulonglong2 a0 = aq0[s], a1 = aq1[s];
            FMA2(accP[0][0], a0.x, x0.x, accP[0][0]);
            FMA2(accP[0][0], a0.y, x0.y, accP[0][0]);
            FMA2(accP[0][1], a0.x, x1.x, accP[0][1]);
            FMA2(accP[0][1], a0.y, x1.y, accP[0][1]);
            FMA2(accP[1][0], a1.x, x0.x, accP[1][0]);
            FMA2(accP[1][0], a1.y, x0.y, accP[1][0]);
            FMA2(accP[1][1], a1.x, x1.x, accP[1][1]);
            FMA2(accP[1][1], a1.y, x1.y, accP[1][1]);
        }
        #pragma unroll
        for (int qi = 0; qi < 2; ++qi) {
            float c = sCorr[(il + qi * 16) * 4 + jt];
            u64 c2; PK(c2, c, c);
            FMA2(acc[qi][0], accP[qi][0], c2, acc[qi][0]);
            FMA2(acc[qi][1], accP[qi][1], c2, acc[qi][1]);
        }
    }

    __syncthreads();
    #pragma unroll
    for (int qi = 0; qi < 2; ++qi) {
        #pragma unroll
        for (int qw = 0; qw < 2; ++qw) {
            float lo, hi; UNPK(lo, hi, acc[qi][qw]);
            float s = lo + hi;
            sOut[(tw + qw * 16) * CP + il + qi * 16] = 1.0f / (1.0f + __expf(-s));
        }
    }
    __syncthreads();
    for (int idx = t; idx < 32 * 32; idx += 256) {
        int r = idx >> 5, c = idx & 31;
        out[((size_t)b * WIN + w0 + r) * KF + i0 + c] = sOut[r * CP + c];
    }
}

// ============================================================================
extern "C" void kernel_launch(void* const* d_in, const int* in_sizes, int n_in,
                              void* d_out, int out_size)
{
    const float* x   = (const float*)d_in[0];
    const float* lw  = (const float*)d_in[1];
    const float* lb  = (const float*)d_in[2];
    const float* a   = (const float*)d_in[3];
    const float* ab  = (const float*)d_in[4];
    float* out = (float*)d_out;

    const int smemA = (64 * XP + 64 * XP) * 4;                       // ~67.6 KB
    const int smemB = (32 * BP + 64 * BP + 256 + 32 + 64) * 4;       // ~99 KB

    cudaFuncSetAttribute(gemmA, cudaFuncAttributeMaxDynamicSharedMemorySize, smemA);
    cudaFuncSetAttribute(kernB, cudaFuncAttributeMaxDynamicSharedMemorySize, smemB);

    gemmA<<<dim3(8, 64), 256, smemA>>>(x, lw, lb);
    kernB<<<dim3(4, 8, NB), 256, smemB>>>(a, ab);
    kernC<<<dim3(8, 4, NB), 256>>>(x, out);
}

// round 11
// speedup vs baseline: 1.0473x; 1.0473x over previous
#include <cuda_runtime.h>
#include <cuda_bf16.h>
#include <cstdint>

#define NB   16
#define WIN  128
#define KF   256
#define EMB  256

typedef unsigned long long u64;

#define ADD2(d, a, b) asm("add.rn.f32x2 %0, %1, %2;" : "=l"(d) : "l"(a), "l"(b))
#define FMA2(d, a, b, c) asm("fma.rn.f32x2 %0, %1, %2, %3;" : "=l"(d) : "l"(a), "l"(b), "l"(c))
#define UNPK(lo, hi, v) asm("mov.b64 {%0, %1}, %2;" : "=f"(lo), "=f"(hi) : "l"(v))
#define PK(d, lo, hi) asm("mov.b64 %0, {%1, %2};" : "=l"(d) : "f"(lo), "f"(hi))
#define ABSMASK 0x7FFFFFFF7FFFFFFFull

// bf16 mma.sync (sm_80+; works on base sm_100 — tcgen05 is sm_100a-only)
#define MMA16816(d, a, b0v, b1v) \
    asm volatile("mma.sync.aligned.m16n8k16.row.col.f32.bf16.bf16.f32 " \
        "{%0,%1,%2,%3}, {%4,%5,%6,%7}, {%8,%9}, {%0,%1,%2,%3};" \
        : "+f"((d)[0]), "+f"((d)[1]), "+f"((d)[2]), "+f"((d)[3]) \
        : "r"((a)[0]), "r"((a)[1]), "r"((a)[2]), "r"((a)[3]), "r"(b0v), "r"(b1v))

// ---------------- device scratch --------------------------------------------
__device__ float g_UI[NB * KF * EMB];
__device__ float g_HJ[NB * KF * EMB];
__device__ float g_ATT[NB * KF * KF];
__device__ float g_MS[NB * KF * 4 * 2];

// ============================================================================
// gemmA_mma: UI/HJ via mma.sync bf16, 3-term split (hh + hl + lh), fp32 acc.
// CTA: 128 rows x 128 e', K=128. 8 warps (4m x 2n), each 32m x 64n.
// smem: A/B hi/lo, row-major [r][PITCH] bf16, direct LDS fragment loads.
// ============================================================================
#define PITCH 136                         // bf16 elems; 272B rows, frag-conflict-free
#define ASZ   (128 * PITCH)               // elems per array
#define SM_GA_TOTAL (4 * ASZ * 2)         // 139264 B

__global__ __launch_bounds__(256)
void gemmA_mma(const float* __restrict__ x, const float* __restrict__ lw,
               const float* __restrict__ lb)
{
    extern __shared__ __nv_bfloat16 sg[];
    __nv_bfloat16* sAhi = sg;
    __nv_bfloat16* sAlo = sAhi + ASZ;
    __nv_bfloat16* sBhi = sAlo + ASZ;
    __nv_bfloat16* sBlo = sBhi + ASZ;

    const int t = threadIdx.x;
    const int rtile = blockIdx.y;             // 0..31
    const int b  = rtile >> 1;
    const int k0 = (rtile & 1) * 128;
    const int ep = blockIdx.x * 128;          // 0,128,256,384
    const int side = (ep >= 256);
    const int eb   = ep & 255;
    const int woff = side ? WIN : 0;

    // ---- fill A = x^T slice [m][w], B = W slice [n][w], bf16 hi/lo ---------
    const float* xb = x + (size_t)b * WIN * KF + k0;
    for (int idx = t; idx < 128 * 128; idx += 256) {
        int m = idx & 127, k = idx >> 7;          // coalesced in m
        float v = xb[k * KF + m];
        __nv_bfloat16 h = __float2bfloat16_rn(v);
        __nv_bfloat16 l = __float2bfloat16_rn(v - __bfloat162float(h));
        sAhi[m * PITCH + k] = h;
        sAlo[m * PITCH + k] = l;
    }
    for (int idx = t; idx < 128 * 128; idx += 256) {
        int k = idx & 127, n = idx >> 7;          // coalesced in k
        float v = lw[(eb + n) * (2 * WIN) + woff + k];
        __nv_bfloat16 h = __float2bfloat16_rn(v);
        __nv_bfloat16 l = __float2bfloat16_rn(v - __bfloat162float(h));
        sBhi[n * PITCH + k] = h;
        sBlo[n * PITCH + k] = l;
    }
    __syncthreads();

    // ---- warp tiling -------------------------------------------------------
    const int wid = t >> 5, lane = t & 31;
    const int gid = lane >> 2, q = lane & 3;
    const int m0 = (wid & 3) * 32;            // 2 m-tiles of 16
    const int n0 = (wid >> 2) * 64;           // 8 n-tiles of 8

    float acc[2][8][4];
    #pragma unroll
    for (int mt = 0; mt < 2; ++mt)
        #pragma unroll
        for (int nt = 0; nt < 8; ++nt)
            #pragma unroll
            for (int r = 0; r < 4; ++r) acc[mt][nt][r] = 0.f;

    #pragma unroll 1
    for (int s = 0; s < 3; ++s) {
        const __nv_bfloat16* pa = (s == 2) ? sAlo : sAhi;
        const __nv_bfloat16* pb = (s == 1) ? sBlo : sBhi;
        #pragma unroll 1
        for (int ks = 0; ks < 8; ++ks) {
            const int kb = ks * 16 + q * 2;
            uint32_t afr[2][4];
            #pragma unroll
            for (int mt = 0; mt < 2; ++mt) {
                const __nv_bfloat16* ab = pa + (m0 + mt * 16 + gid) * PITCH + kb;
                afr[mt][0] = *(const uint32_t*)(ab);
                afr[mt][1] = *(const uint32_t*)(ab + 8 * PITCH);
                afr[mt][2] = *(const uint32_t*)(ab + 8);
                afr[mt][3] = *(const uint32_t*)(ab + 8 * PITCH + 8);
            }
            #pragma unroll
            for (int nt = 0; nt < 8; ++nt) {
                const __nv_bfloat16* bb = pb + (n0 + nt * 8 + gid) * PITCH + kb;
                uint32_t b0 = *(const uint32_t*)(bb);
                uint32_t b1 = *(const uint32_t*)(bb + 8);
                MMA16816(acc[0][nt], afr[0], b0, b1);
                MMA16816(acc[1][nt], afr[1], b0, b1);
            }
        }
    }

    // ---- epilogue: stage in smem (reuse), coalesced store ------------------
    float* sStage = (float*)sg;               // [128][132] = 67.6KB < 139KB
    __syncthreads();
    #pragma unroll
    for (int mt = 0; mt < 2; ++mt) {
        #pragma unroll
        for (int nt = 0; nt < 8; ++nt) {
            int row = m0 + mt * 16 + gid;
            int col = n0 + nt * 8 + q * 2;
            sStage[row * 132 + col]           = acc[mt][nt][0];
            sStage[row * 132 + col + 1]       = acc[mt][nt][1];
            sStage[(row + 8) * 132 + col]     = acc[mt][nt][2];
            sStage[(row + 8) * 132 + col + 1] = acc[mt][nt][3];
        }
    }
    __syncthreads();
    float* dst = (side ? g_HJ : g_UI) + ((size_t)b * KF + k0) * EMB + eb;
    for (int idx = t; idx < 128 * 128; idx += 256) {
        int r = idx >> 7, c = idx & 127;          // coalesced in c
        float v = sStage[r * 132 + c];
        if (!side) v += __ldg(lb + eb + c);
        dst[(size_t)r * EMB + c] = v;
    }
}

// ============================================================================
// kernB: e = 0.6(dot_i+dot_j) + sum 0.4a|u+v| + bias; store exp(e - m_tile);
// partials -> g_MS.
// ============================================================================
#define BP 260
__global__ __launch_bounds__(256, 2)
void kernB(const float* __restrict__ a, const float* __restrict__ ab)
{
    extern __shared__ float sm[];
    float* sUI = sm;
    float* sHJ = sUI + 32 * BP;
    float* sA4 = sHJ + 64 * BP;
    float* sAI = sA4 + 256;
    float* sAJ = sAI + 32;

    const int b  = blockIdx.z;
    const int i0 = blockIdx.y * 32;
    const int jt = blockIdx.x;
    const int j0 = jt * 64;
    const int t  = threadIdx.x;

    const float4* gu = (const float4*)(g_UI + ((size_t)b * KF + i0) * EMB);
    for (int idx = t; idx < 32 * 64; idx += 256) {
        int r = idx >> 6, c = idx & 63;
        *(float4*)(sUI + r * BP + c * 4) = gu[r * 64 + c];
    }
    const float4* gh = (const float4*)(g_HJ + ((size_t)b * KF + j0) * EMB);
    for (int idx = t; idx < 64 * 64; idx += 256) {
        int r = idx >> 6, c = idx & 63;
        *(float4*)(sHJ + r * BP + c * 4) = gh[r * 64 + c];
    }
    sA4[t] = 0.4f * a[t];
    __syncthreads();

    {
        const int warp = t >> 5, lane = t & 31;
        #pragma unroll
        for (int rr = 0; rr < 4; ++rr) {
            int r = warp * 4 + rr;
            float s = 0.f;
            #pragma unroll
            for (int q = 0; q < 8; ++q) s += sUI[r * BP + lane + q * 32] * sA4[lane + q * 32];
            #pragma unroll
            for (int off = 16; off; off >>= 1) s += __shfl_xor_sync(0xffffffffu, s, off);
            if (lane == 0) sAI[r] = 1.5f * s;
        }
        #pragma unroll
        for (int rr = 0; rr < 8; ++rr) {
            int r = warp * 8 + rr;
            float s = 0.f;
            #pragma unroll
            for (int q = 0; q < 8; ++q) s += sHJ[r * BP + lane + q * 32] * sA4[lane + q * 32];
            #pragma unroll
            for (int off = 16; off; off >>= 1) s += __shfl_xor_sync(0xffffffffu, s, off);
            if (lane == 0) sAJ[r] = 1.5f * s;
        }
    }
    __syncthreads();

    const int ti = t >> 4;
    const int jl = t & 15;
    const ulonglong2* uq0 = (const ulonglong2*)(sUI + ti * BP);
    const ulonglong2* uq1 = (const ulonglong2*)(sUI + (ti + 16) * BP);
    const ulonglong2* vq[4];
    #pragma unroll
    for (int q = 0; q < 4; ++q) vq[q] = (const ulonglong2*)(sHJ + (jl + q * 16) * BP);
    const ulonglong2* aq = (const ulonglong2*)sA4;

    u64 acc0[4], acc1[4];
    #pragma unroll
    for (int q = 0; q < 4; ++q) { acc0[q] = 0ull; acc1[q] = 0ull; }

    #pragma unroll 2
    for (int s = 0; s < 64; ++s) {
        ulonglong2 ae = aq[s], u0 = uq0[s], u1 = uq1[s];
        #pragma unroll
        for (int q = 0; q < 4; ++q) {
            ulonglong2 v = vq[q][s];
            u64 s0x, s0y, s1x, s1y;
            ADD2(s0x, u0.x, v.x); ADD2(s0y, u0.y, v.y);
            ADD2(s1x, u1.x, v.x); ADD2(s1y, u1.y, v.y);
            s0x &= ABSMASK; s0y &= ABSMASK;
            s1x &= ABSMASK; s1y &= ABSMASK;
            FMA2(acc0[q], s0x, ae.x, acc0[q]);
            FMA2(acc0[q], s0y, ae.y, acc0[q]);
            FMA2(acc1[q], s1x, ae.x, acc1[q]);
            FMA2(acc1[q], s1y, ae.y, acc1[q]);
        }
    }

    const float ai0 = sAI[ti], ai1 = sAI[ti + 16];
    float v0[4], v1[4];
    #pragma unroll
    for (int q = 0; q < 4; ++q) {
        int jc = jl + q * 16;
        int j  = j0 + jc;
        float lo, hi;
        UNPK(lo, hi, acc0[q]);
        v0[q] = lo + hi + ai0 + sAJ[jc] + ab[(size_t)(i0 + ti) * KF + j];
        UNPK(lo, hi, acc1[q]);
        v1[q] = lo + hi + ai1 + sAJ[jc] + ab[(size_t)(i0 + ti + 16) * KF + j];
    }
    float m0 = fmaxf(fmaxf(v0[0], v0[1]), fmaxf(v0[2], v0[3]));
    float m1 = fmaxf(fmaxf(v1[0], v1[1]), fmaxf(v1[2], v1[3]));
    #pragma unroll
    for (int off = 8; off; off >>= 1) {
        m0 = fmaxf(m0, __shfl_xor_sync(0xffffffffu, m0, off));
        m1 = fmaxf(m1, __shfl_xor_sync(0xffffffffu, m1, off));
    }
    float e0[4], e1[4];
    float s0 = 0.f, s1 = 0.f;
    #pragma unroll
    for (int q = 0; q < 4; ++q) {
        e0[q] = __expf(v0[q] - m0); s0 += e0[q];
        e1[q] = __expf(v1[q] - m1); s1 += e1[q];
    }
    #pragma unroll
    for (int off = 8; off; off >>= 1) {
        s0 += __shfl_xor_sync(0xffffffffu, s0, off);
        s1 += __shfl_xor_sync(0xffffffffu, s1, off);
    }
    if (jl == 0) {
        size_t r0i = (size_t)(b * KF + i0 + ti) * 8 + jt * 2;
        size_t r1i = (size_t)(b * KF + i0 + ti + 16) * 8 + jt * 2;
        g_MS[r0i] = m0; g_MS[r0i + 1] = s0;
        g_MS[r1i] = m1; g_MS[r1i + 1] = s1;
    }

    float* sE = sm;
    __syncthreads();
    #pragma unroll
    for (int q = 0; q < 4; ++q) {
        int jc = jl + q * 16;
        sE[ti * 66 + jc]        = e0[q];
        sE[(ti + 16) * 66 + jc] = e1[q];
    }
    __syncthreads();
    for (int idx = t; idx < 32 * 64; idx += 256) {
        int r = idx >> 6, c = idx & 63;
        g_ATT[((size_t)b * KF + i0 + r) * KF + j0 + c] = sE[r * 66 + c];
    }
}

// ============================================================================
// kernC: out = sigmoid( sum_jt corr * (att' @ x) )
// ============================================================================
#define CP 68
__global__ __launch_bounds__(256)
void kernC(const float* __restrict__ x, float* __restrict__ out)
{
    __shared__ float sAtt[64 * CP];
    __shared__ float sX[32 * CP];
    __shared__ float sOut[32 * CP];
    __shared__ float sCorr[64 * 4];

    const int b  = blockIdx.z;
    const int w0 = blockIdx.y * 32;
    const int i0 = blockIdx.x * 64;
    const int t  = threadIdx.x;
    const int il = t & 15;
    const int tw = t >> 4;

    if (t < 64) {
        const float* p = g_MS + (size_t)(b * KF + i0 + t) * 8;
        float m[4], s[4];
        #pragma unroll
        for (int q = 0; q < 4; ++q) { m[q] = p[q * 2]; s[q] = p[q * 2 + 1]; }
        float M = fmaxf(fmaxf(m[0], m[1]), fmaxf(m[2], m[3]));
        float ex[4];
        float S = 0.f;
        #pragma unroll
        for (int q = 0; q < 4; ++q) { ex[q] = __expf(m[q] - M); S += s[q] * ex[q]; }
        float inv = 1.0f / S;
        #pragma unroll
        for (int q = 0; q < 4; ++q) sCorr[t * 4 + q] = ex[q] * inv;
    }

    u64 acc[4][2];
    #pragma unroll
    for (int qi = 0; qi < 4; ++qi) { acc[qi][0] = 0ull; acc[qi][1] = 0ull; }

    for (int jt = 0; jt < 4; ++jt) {
        __syncthreads();
        const int j0 = jt * 64;
        for (int idx = t; idx < 64 * 16; idx += 256) {
            int r = idx >> 4, c = idx & 15;
            *(float4*)(sAtt + r * CP + c * 4) =
                *(const float4*)(g_ATT + ((size_t)b * KF + i0 + r) * KF + j0 + c * 4);
        }
        for (int idx = t; idx < 32 * 16; idx += 256) {
            int r = idx >> 4, c = idx & 15;
            *(float4*)(sX + r * CP + c * 4) =
                *(const float4*)(x + ((size_t)b * WIN + w0 + r) * KF + j0 + c * 4);
        }
        __syncthreads();

        const ulonglong2* xq0 = (const ulonglong2*)(sX + tw * CP);
        const ulonglong2* xq1 = (const ulonglong2*)(sX + (tw + 16) * CP);
        const ulonglong2* aq[4];
        #pragma unroll
        for (int qi = 0; qi < 4; ++qi) aq[qi] = (const ulonglong2*)(sAtt + (il + qi * 16) * CP);

        u64 accP[4][2];
        #pragma unroll
        for (int qi = 0; qi < 4; ++qi) { accP[qi][0] = 0ull; accP[qi][1] = 0ull; }

        #pragma unroll 4
        for (int s = 0; s < 16; ++s) {
            ulonglong2 x0 = xq0[s], x1 = xq1[s];
            #pragma unroll
            for (int qi = 0; qi < 4; ++qi) {
                ulonglong2 av = aq[qi][s];
                FMA2(accP[qi][0], av.x, x0.x, accP[qi][0]);
                FMA2(accP[qi][0], av.y, x0.y, accP[qi][0]);
                FMA2(accP[qi][1], av.x, x1.x, accP[qi][1]);
                FMA2(accP[qi][1], av.y, x1.y, accP[qi][1]);
            }
        }
        #pragma unroll
        for (int qi = 0; qi < 4; ++qi) {
            float c = sCorr[(il + qi * 16) * 4 + jt];
            u64 c2; PK(c2, c, c);
            FMA2(acc[qi][0], accP[qi][0], c2, acc[qi][0]);
            FMA2(acc[qi][1], accP[qi][1], c2, acc[qi][1]);
        }
    }

    __syncthreads();
    #pragma unroll
    for (int qi = 0; qi < 4; ++qi) {
        #pragma unroll
        for (int qw = 0; qw < 2; ++qw) {
            float lo, hi; UNPK(lo, hi, acc[qi][qw]);
            float s = lo + hi;
            sOut[(tw + qw * 16) * CP + il + qi * 16] = 1.0f / (1.0f + __expf(-s));
        }
    }
    __syncthreads();
    for (int idx = t; idx < 32 * 64; idx += 256) {
        int r = idx >> 6, c = idx & 63;
        out[((size_t)b * WIN + w0 + r) * KF + i0 + c] = sOut[r * CP + c];
    }
}

// ============================================================================
extern "C" void kernel_launch(void* const* d_in, const int* in_sizes, int n_in,
                              void* d_out, int out_size)
{
    const float* x   = (const float*)d_in[0];
    const float* lw  = (const float*)d_in[1];
    const float* lb  = (const float*)d_in[2];
    const float* a   = (const float*)d_in[3];
    const float* ab  = (const float*)d_in[4];
    float* out = (float*)d_out;

    const int smemB = (32 * BP + 64 * BP + 256 + 32 + 64) * 4;

    cudaFuncSetAttribute(gemmA_mma, cudaFuncAttributeMaxDynamicSharedMemorySize, SM_GA_TOTAL);
    cudaFuncSetAttribute(kernB, cudaFuncAttributeMaxDynamicSharedMemorySize, smemB);

    gemmA_mma<<<dim3(4, 32), 256, SM_GA_TOTAL>>>(x, lw, lb);
    kernB<<<dim3(4, 8, NB), 256, smemB>>>(a, ab);
    kernC<<<dim3(4, 4, NB), 256>>>(x, out);
}